// round 8
// baseline (speedup 1.0000x reference)
#include <cuda_runtime.h>

#define BB 8
#define NSEQ 256
#define DD 300
#define KHALF 150
#define MROWS (BB*NSEQ)          // 2048
#define FEATW 512                // left | right | hs | he

typedef unsigned long long ull;

// Raw K-half partials of x @ [Wl|Wr|Ws1|We1]^T (no bias, no relu).
__device__ float g_part0[MROWS * FEATW];
__device__ float g_part1[MROWS * FEATW];

// ---- packed f32x2 helpers (sm_100+) --------------------------------------
__device__ __forceinline__ ull f2_pack(float x, float y) {
    ull r; asm("mov.b64 %0, {%1,%2};" : "=l"(r) : "f"(x), "f"(y)); return r;
}
__device__ __forceinline__ float2 f2_unpack(ull v) {
    float2 r; asm("mov.b64 {%0,%1}, %2;" : "=f"(r.x), "=f"(r.y) : "l"(v)); return r;
}
#define FMA2(d,a,b,c) asm("fma.rn.f32x2 %0, %1, %2, %3;" : "=l"(d) : "l"(a), "l"(b), "l"(c))
#define ADD2(d,a,b)   asm("add.rn.f32x2 %0, %1, %2;"     : "=l"(d) : "l"(a), "l"(b))

// ---------------------------------------------------------------------------
// Kernel 1: fused gather + GEMM partials.  [2048 x 150] @ [150 x 512] x2
// grid (16 Mtiles, 8 Ntiles, 2 K-halves), 256 thr, 2 CTAs/SM target.
// BM=128, BN=64, BK=30 (150 = 5*30). f32x2 pairs over M; B duplicated (b,b)
// in smem, fetched as warp-uniform broadcast LDS.128 (ulonglong2).
// Inner loop per k: 2 LDS.64 + 4 bcast LDS.128 + 16 FFMA2, zero packs.
// ---------------------------------------------------------------------------
__global__ __launch_bounds__(256, 2) void gemm_kernel(
    const int*   __restrict__ sent, const float* __restrict__ emb,
    const float* __restrict__ Wl,   const float* __restrict__ Wr,
    const float* __restrict__ Ws1,  const float* __restrict__ We1)
{
    const int BK = 30, PADA = 132, PADB = 132;
    __shared__ __align__(16) float As[2][BK * PADA];   // [k][m]      128 used
    __shared__ __align__(16) float Bs[2][BK * PADB];   // [k][2n dup] 128 used
    __shared__ int rowidx[128];

    const int m0  = blockIdx.x * 128;
    const int n0  = blockIdx.y * 64;
    const int z   = blockIdx.z;          // K half
    const int kz  = z * KHALF;
    const int seg = n0 >> 7;             // 0:left 1:right 2:hs 3:he
    const int nl0 = n0 & 127;

    const float* W;
    if      (seg == 0) W = Wl;
    else if (seg == 1) W = Wr;
    else if (seg == 2) W = Ws1;
    else               W = We1;
    float* gout = z ? g_part1 : g_part0;

    const int tid = threadIdx.x;
    if (tid < 128) rowidx[tid] = sent[m0 + tid];
    __syncthreads();

    // register prefetch: A tile 128x30 = 3840 = 15*256; B tile 64x30 = 1920
    float aR[15], bR[8];
    #pragma unroll
    for (int i = 0; i < 15; i++) {
        int idx = i * 256 + tid; int m = idx / 30; int k = idx - m * 30;
        aR[i] = emb[(long)rowidx[m] * DD + kz + k];
    }
    #pragma unroll
    for (int i = 0; i < 8; i++) {
        int idx = i * 256 + tid;
        if (idx < 1920) { int n = idx / 30; int k = idx - n * 30; bR[i] = W[(nl0 + n) * DD + kz + k]; }
    }

    const int lane = tid & 31;
    const int wid  = tid >> 5;           // warp -> 8 n-columns
    ull acc0[8], acc1[8];
    #pragma unroll
    for (int i = 0; i < 8; i++) { acc0[i] = 0ull; acc1[i] = 0ull; }

    for (int t = 0; t < 5; t++) {
        const int c = t & 1;
        #pragma unroll
        for (int i = 0; i < 15; i++) {
            int idx = i * 256 + tid; int m = idx / 30; int k = idx - m * 30;
            As[c][k * PADA + m] = aR[i];
        }
        #pragma unroll
        for (int i = 0; i < 8; i++) {
            int idx = i * 256 + tid;
            if (idx < 1920) { int n = idx / 30; int k = idx - n * 30;
                *(ull*)&Bs[c][k * PADB + 2 * n] = f2_pack(bR[i], bR[i]); }
        }
        __syncthreads();

        // prefetch next tile while computing on this one
        if (t < 4) {
            const int k0 = kz + (t + 1) * BK;
            #pragma unroll
            for (int i = 0; i < 15; i++) {
                int idx = i * 256 + tid; int m = idx / 30; int k = idx - m * 30;
                aR[i] = emb[(long)rowidx[m] * DD + k0 + k];
            }
            #pragma unroll
            for (int i = 0; i < 8; i++) {
                int idx = i * 256 + tid;
                if (idx < 1920) { int n = idx / 30; int k = idx - n * 30; bR[i] = W[(nl0 + n) * DD + k0 + k]; }
            }
        }

        #pragma unroll
        for (int k = 0; k < BK; k++) {
            const ull a0 = *(const ull*)&As[c][k * PADA + 2 * lane];       // (m, m+1)
            const ull a1 = *(const ull*)&As[c][k * PADA + 64 + 2 * lane];
            const ulonglong2* bp = (const ulonglong2*)&Bs[c][k * PADB + 16 * wid]; // bcast
            const ulonglong2 b01 = bp[0], b23 = bp[1], b45 = bp[2], b67 = bp[3];
            ull b[8] = {b01.x, b01.y, b23.x, b23.y, b45.x, b45.y, b67.x, b67.y};
            #pragma unroll
            for (int n = 0; n < 8; n++) {
                FMA2(acc0[n], a0, b[n], acc0[n]);
                FMA2(acc1[n], a1, b[n], acc1[n]);
            }
        }
        // next iter writes the other buffer; its __syncthreads guards reuse
    }

    // epilogue: raw partial store (bias/relu applied by consumers)
    #pragma unroll
    for (int half = 0; half < 2; half++) {
        const ull* ac = half ? acc1 : acc0;
        const int mbase = m0 + half * 64 + 2 * lane;
        float2 u[8];
        #pragma unroll
        for (int n = 0; n < 8; n++) u[n] = f2_unpack(ac[n]);
        float* o0 = &gout[(long)mbase * FEATW + n0 + 8 * wid];
        float* o1 = o0 + FEATW;
        *(float4*)&o0[0] = make_float4(u[0].x, u[1].x, u[2].x, u[3].x);
        *(float4*)&o0[4] = make_float4(u[4].x, u[5].x, u[6].x, u[7].x);
        *(float4*)&o1[0] = make_float4(u[0].y, u[1].y, u[2].y, u[3].y);
        *(float4*)&o1[4] = make_float4(u[4].y, u[5].y, u[6].y, u[7].y);
    }
}

// ---------------------------------------------------------------------------
// Kernel 2: start/end heads. One warp per row; fuses partial sum + bias + relu.
// ---------------------------------------------------------------------------
__global__ __launch_bounds__(256) void startend_kernel(
    const float* __restrict__ bs1, const float* __restrict__ be1,
    const float* __restrict__ Ws2, const float* __restrict__ bs2,
    const float* __restrict__ We2, const float* __restrict__ be2,
    float* __restrict__ out)
{
    const int warp = blockIdx.x * 8 + (threadIdx.x >> 5);
    const int lane = threadIdx.x & 31;
    const float* h0 = &g_part0[warp * FEATW + 256];
    const float* h1 = &g_part1[warp * FEATW + 256];
    float s = 0.f, e = 0.f;
    #pragma unroll
    for (int u = 0; u < 4; u++) {
        const int p = lane + u * 32;
        s += fmaxf(h0[p]       + h1[p]       + bs1[p], 0.f) * Ws2[p];
        e += fmaxf(h0[p + 128] + h1[p + 128] + be1[p], 0.f) * We2[p];
    }
    #pragma unroll
    for (int o = 16; o; o >>= 1) {
        s += __shfl_xor_sync(0xFFFFFFFFu, s, o);
        e += __shfl_xor_sync(0xFFFFFFFFu, e, o);
    }
    if (lane == 0) {
        out[BB * NSEQ * NSEQ + warp]         = s + bs2[0];
        out[BB * NSEQ * NSEQ + MROWS + warp] = e + be2[0];
    }
}

// ---------------------------------------------------------------------------
// Kernel 3: bigram = relu((left+bl)[b,j,:] + right[b,i,:]) . Wo + bo
// thread = one i (128 per block), 16 j per block; partial sums fused at read.
// left(+bl) staged in smem (bcast reads), right combined into registers.
// grid (16 jtiles, 2 itiles, 8 b), 128 threads.
// ---------------------------------------------------------------------------
__global__ __launch_bounds__(128) void bigram_kernel(
    const float* __restrict__ bl,
    const float* __restrict__ Wo, const float* __restrict__ bo,
    float* __restrict__ out)
{
    __shared__ __align__(16) float Ls[2176];   // 16j x 128p; reused as 128x17 transpose
    __shared__ __align__(16) float wos[128];

    const int b  = blockIdx.z;
    const int i0 = blockIdx.y * 128;
    const int j0 = blockIdx.x * 16;
    const int tid = threadIdx.x;

    // stage left tile [16 j][128 p] = p0 + p1 + bl
    for (int idx = tid; idx < 512; idx += 128) {
        const int r = idx >> 5, c4 = idx & 31;
        const long off = (long)(b * NSEQ + j0 + r) * FEATW + c4 * 4;
        const float4 a = *(const float4*)&g_part0[off];
        const float4 c = *(const float4*)&g_part1[off];
        const float4 bb = *(const float4*)&bl[c4 * 4];
        *(float4*)&Ls[r * 128 + c4 * 4] =
            make_float4(a.x + c.x + bb.x, a.y + c.y + bb.y,
                        a.z + c.z + bb.z, a.w + c.w + bb.w);
    }
    wos[tid] = Wo[tid];
    __syncthreads();

    const int i = i0 + tid;
    const float* r0row = &g_part0[(long)(b * NSEQ + i) * FEATW + 128];
    const float* r1row = &g_part1[(long)(b * NSEQ + i) * FEATW + 128];

    ull acc[16];
    #pragma unroll
    for (int j = 0; j < 16; j++) acc[j] = 0ull;

    // right chunk double buffer (16 p = 4 float4 per partial)
    float4 rA[4], rB[4], rnA[4], rnB[4];
    #pragma unroll
    for (int q = 0; q < 4; q++) { rA[q] = *(const float4*)&r0row[q * 4];
                                  rB[q] = *(const float4*)&r1row[q * 4]; }

    for (int pc = 0; pc < 8; pc++) {
        if (pc < 7) {
            #pragma unroll
            for (int q = 0; q < 4; q++) {
                rnA[q] = *(const float4*)&r0row[(pc + 1) * 16 + q * 4];
                rnB[q] = *(const float4*)&r1row[(pc + 1) * 16 + q * 4];
            }
        }
        // combine right partials: 8 packed pairs
        ull rv[8];
        {
            const ull* ua = (const ull*)rA;
            const ull* ub = (const ull*)rB;
            #pragma unroll
            for (int q = 0; q < 8; q++) ADD2(rv[q], ua[q], ub[q]);
        }
        const ull* wv = (const ull*)&wos[pc * 16];           // bcast
        const float* lbase = &Ls[pc * 16];

        #pragma unroll
        for (int up = 0; up < 4; up++) {
            const ull w0 = wv[2 * up], w1 = wv[2 * up + 1];
            const ull r0 = rv[2 * up], r1 = rv[2 * up + 1];
            #pragma unroll
            for (int j = 0; j < 16; j++) {
                const ull* lp = (const ull*)&lbase[j * 128 + 4 * up];  // bcast LDS.128
                ull s0; ADD2(s0, lp[0], r0);
                float2 f0 = f2_unpack(s0);
                f0.x = fmaxf(f0.x, 0.f); f0.y = fmaxf(f0.y, 0.f);
                FMA2(acc[j], f2_pack(f0.x, f0.y), w0, acc[j]);
                ull s1; ADD2(s1, lp[1], r1);
                float2 f1 = f2_unpack(s1);
                f1.x = fmaxf(f1.x, 0.f); f1.y = fmaxf(f1.y, 0.f);
                FMA2(acc[j], f2_pack(f1.x, f1.y), w1, acc[j]);
            }
        }
        #pragma unroll
        for (int q = 0; q < 4; q++) { rA[q] = rnA[q]; rB[q] = rnB[q]; }
    }

    // transpose through smem for coalesced output stores
    __syncthreads();                       // done reading Ls
    const float bov = bo[0];
    #pragma unroll
    for (int j = 0; j < 16; j++) {
        const float2 a = f2_unpack(acc[j]);
        Ls[tid * 17 + j] = a.x + a.y + bov;
    }
    __syncthreads();
    #pragma unroll
    for (int it = 0; it < 4; it++) {
        const int f4 = it * 128 + tid;
        const int r  = f4 >> 2;            // i-local row
        const int jj = (f4 & 3) * 4;
        float4 v = make_float4(Ls[r * 17 + jj], Ls[r * 17 + jj + 1],
                               Ls[r * 17 + jj + 2], Ls[r * 17 + jj + 3]);
        *(float4*)&out[(b * NSEQ + i0 + r) * NSEQ + j0 + jj] = v;
    }
}

// ---------------------------------------------------------------------------
extern "C" void kernel_launch(void* const* d_in, const int* in_sizes, int n_in,
                              void* d_out, int out_size)
{
    const int*   sent = (const int*)  d_in[0];
    const float* emb  = (const float*)d_in[1];
    const float* Wl   = (const float*)d_in[2];
    const float* bl   = (const float*)d_in[3];
    const float* Wr   = (const float*)d_in[4];
    const float* Wo   = (const float*)d_in[5];
    const float* bo   = (const float*)d_in[6];
    const float* Ws1  = (const float*)d_in[7];
    const float* bs1  = (const float*)d_in[8];
    const float* Ws2  = (const float*)d_in[9];
    const float* bs2  = (const float*)d_in[10];
    const float* We1  = (const float*)d_in[11];
    const float* be1  = (const float*)d_in[12];
    const float* We2  = (const float*)d_in[13];
    const float* be2  = (const float*)d_in[14];
    float* out = (float*)d_out;

    dim3 ggrid(16, 8, 2);
    gemm_kernel<<<ggrid, 256>>>(sent, emb, Wl, Wr, Ws1, We1);

    startend_kernel<<<256, 256>>>(bs1, be1, Ws2, bs2, We2, be2, out);

    dim3 bgrid(16, 2, 8);
    bigram_kernel<<<bgrid, 128>>>(bl, Wo, bo, out);
}